// round 14
// baseline (speedup 1.0000x reference)
#include <cuda_runtime.h>
#include <cuda_fp16.h>
#include <math.h>
#include <math_constants.h>

// EM routing, matrix capsules.
// N=4, child 12x12, kernel 3, stride 1 -> P=10, tiles = 4*100 = 400
// K=144 (9 slots x 16 child caps), O=32 parent caps, ch=16 pose dims.
// votes: (400, 144, 32, 16) f32 ; acts: (400, 144) ; beta_v/beta_a: (32)
// Output: poses (400*32*16 = 204800 floats) then activations (400*32).
//
// R14 = R13 (256-thread single-wave CTAs, fp16 votes cache, __ldcs on the
// single-use fp32 stream) + e-step fused back into the consumer mz with
// DOUBLE-BUFFERED z. The __ldcs protection keeps z + fp16 cache L2-resident
// across the launch boundary, so the fused neighbor-z gather is cheap
// coalesced L2 traffic (the R8 fusion failed only because z was in DRAM).

#define NTILES 400
#define KTOT   144
#define OCAPS  32
#define CH     16
#define TILE_ELEMS (KTOT*OCAPS*CH)   // 73728
#define ZPT    (KTOT*OCAPS)          // 4608
#define EPS    1e-9f
#define LNF    22.2222222222222222f  // 100/(144/32)
#define TWO_PI 6.2831853071795864f
#define NCELLS 144                   // 12*12 child cells
#define NT     256

__device__ float g_z [2][NTILES*ZPT];                 // double-buffered (tile, k, o)
__device__ uint4 g_vh[(size_t)NTILES*TILE_ELEMS/8];   // fp16 votes cache (59 MB)

__device__ __forceinline__ float sigmoidf_(float x) { return 1.0f/(1.0f+__expf(-x)); }

template<bool INIT_RR, bool FINAL, int RD>
__global__ void __launch_bounds__(NT)
mz_kernel(const float* __restrict__ votes, const float* __restrict__ acti,
          const float* __restrict__ beta_v, const float* __restrict__ beta_a,
          float lam, float* __restrict__ out)
{
    const int tile = blockIdx.x;
    const int n = tile / 100, p = tile % 100;
    const int pr = p / 10, pc = p % 10;
    const float* V = votes + (size_t)tile * TILE_ELEMS;
    __half* VH = ((__half*)g_vh) + (size_t)tile * TILE_ELEMS;

    __shared__ float w_s[ZPT];           // rr*act  [k][o]
    __shared__ float acti_s[KTOT];
    __shared__ float m_s[KTOT];          // softmax max per k (slot,cc)
    __shared__ float dinv_s[KTOT];
    __shared__ float ps1[4*512];         // pass1 partials [part][o*16+c]
    __shared__ float ps2[4*512];
    __shared__ float rp[16*OCAPS];       // rrs partials
    __shared__ float rrs_s[OCAPS];
    __shared__ float mean_cs[CH*OCAPS];  // [c][o]
    __shared__ float i2v_cs[CH*OCAPS];   // 1/(2 var) [c][o]
    __shared__ float cost_s[OCAPS];
    __shared__ float logact_s[OCAPS];
    __shared__ float op2_s[OCAPS];

    const int t = threadIdx.x;
    if (t < KTOT) acti_s[t] = acti[tile*KTOT + t];

    // ---- fused e-step: m/dinv for this tile's 144 k's (reads z buf RD,
    // written by the PREVIOUS launch; this launch writes only RD^1).
    // 8 warps x 2 rounds cover the 16 warp-roles of the proven R7/R8 code;
    // per-k load order + shuffle reductions bitwise-identical.
    if (!INIT_RR) {
        const float* Zr = g_z[RD];
        const int wi8 = t >> 5, o = t & 31;
        #pragma unroll
        for (int round = 0; round < 2; round++) {
            const int wi = wi8 + 8*round;          // 0..15
            #pragma unroll
            for (int j = 0; j < 9; j++) {
                const int k = wi*9 + j;
                const int slot = k >> 4, ccp = k & 15;
                const int r = pr + slot/3, ccol = pc + slot%3;   // child cell
                float zb[9];
                float m = -CUDART_INF_F;
                #pragma unroll
                for (int dr = 0; dr < 3; dr++) {
                    #pragma unroll
                    for (int dc = 0; dc < 3; dc++) {
                        const int i = dr*3 + dc;
                        const int pr2 = r - dr, pc2 = ccol - dc;
                        if (pr2 >= 0 && pr2 < 10 && pc2 >= 0 && pc2 < 10) {
                            const int p2 = pr2*10 + pc2;
                            zb[i] = Zr[((size_t)(n*100 + p2))*ZPT + (i*CH + ccp)*OCAPS + o];
                            m = fmaxf(m, zb[i]);
                        } else {
                            zb[i] = -CUDART_INF_F;
                        }
                    }
                }
                #pragma unroll
                for (int off = 16; off > 0; off >>= 1)
                    m = fmaxf(m, __shfl_xor_sync(0xffffffffu, m, off));
                if (isinf(m)) m = 0.0f;

                float s = 0.f;
                #pragma unroll
                for (int i = 0; i < 9; i++)
                    s += __expf(zb[i] - m);
                #pragma unroll
                for (int off = 16; off > 0; off >>= 1)
                    s += __shfl_xor_sync(0xffffffffu, s, off);

                if (o == 0) { m_s[k] = m; dinv_s[k] = 1.0f / s; }
            }
        }
    }
    __syncthreads();

    // ---- build w = rr * act_i ----
    if (INIT_RR) {
        for (int idx = t; idx < ZPT; idx += NT) {
            int k = idx >> 5;
            int slot = k >> 4;
            int r = pr + slot/3, c = pc + slot%3;
            int cr = min(r,9) - max(0,r-2) + 1;
            int cc = min(c,9) - max(0,c-2) + 1;
            float rrv = 1.0f / ((float)(cr*cc) * (float)OCAPS + EPS);
            w_s[idx] = rrv * acti_s[k];
        }
    } else {
        const float* Zown = g_z[RD] + (size_t)tile * ZPT;
        for (int idx = t; idx < ZPT; idx += NT) {
            int k = idx >> 5;
            w_s[idx] = __expf(Zown[idx] - m_s[k]) * dinv_s[k] * acti_s[k];
        }
    }
    __syncthreads();

    // ---- rrs partials: 8 warps x 2 rounds cover 16 segs ----
    {
        const int o = t & 31, w = t >> 5;          // w in 0..7
        #pragma unroll
        for (int round = 0; round < 2; round++) {
            const int seg = w + 8*round;
            float sp = 0.f;
            #pragma unroll
            for (int j = 0; j < 9; j++) sp += w_s[(seg*9 + j)*OCAPS + o];
            rp[seg*OCAPS + o] = sp;
        }
    }
    __syncthreads();
    if (t < OCAPS) {
        float s = 0.f;
        #pragma unroll
        for (int i = 0; i < 16; i++) s += rp[i*OCAPS + t];
        rrs_s[t] = s;
    }

    // ---- pass 1: 2 rounds, each = one old (part,o,cq) slot ----
    {
        #pragma unroll
        for (int round = 0; round < 2; round++) {
            const int slot = t + NT*round;          // 0..511
            const int cq = slot & 3, o1 = (slot >> 2) & 31, part = slot >> 7;
            float4 s1 = make_float4(0.f,0.f,0.f,0.f);
            float4 s2 = make_float4(0.f,0.f,0.f,0.f);
            const int kbeg = part * 36;
            if (INIT_RR) {
                const float4* V4 = (const float4*)V;
                for (int kb = 0; kb < 36; kb += 6) {
                    float4 vv[6];
                    #pragma unroll
                    for (int g = 0; g < 6; g++)
                        vv[g] = __ldcs(&V4[(kbeg + kb + g)*128 + o1*4 + cq]);  // evict-first single-use stream
                    #pragma unroll
                    for (int g = 0; g < 6; g++) {
                        const int k = kbeg + kb + g;
                        const float4 v = vv[g];
                        const float w = w_s[k*OCAPS + o1];
                        s1.x = fmaf(w, v.x, s1.x); s2.x = fmaf(w*v.x, v.x, s2.x);
                        s1.y = fmaf(w, v.y, s1.y); s2.y = fmaf(w*v.y, v.y, s2.y);
                        s1.z = fmaf(w, v.z, s1.z); s2.z = fmaf(w*v.z, v.z, s2.z);
                        s1.w = fmaf(w, v.w, s1.w); s2.w = fmaf(w*v.w, v.w, s2.w);
                        union { __half2 h[2]; uint2 u; } cv;
                        cv.h[0] = __floats2half2_rn(v.x, v.y);
                        cv.h[1] = __floats2half2_rn(v.z, v.w);
                        *(uint2*)(VH + k*512 + o1*16 + cq*4) = cv.u;
                    }
                }
            } else {
                for (int kb = 0; kb < 36; kb += 6) {
                    uint2 hv[6];
                    #pragma unroll
                    for (int g = 0; g < 6; g++)
                        hv[g] = *(const uint2*)(VH + (kbeg + kb + g)*512 + o1*16 + cq*4);
                    #pragma unroll
                    for (int g = 0; g < 6; g++) {
                        const int k = kbeg + kb + g;
                        union { uint2 u; __half2 h[2]; } cv; cv.u = hv[g];
                        float2 f01 = __half22float2(cv.h[0]);
                        float2 f23 = __half22float2(cv.h[1]);
                        const float w = w_s[k*OCAPS + o1];
                        s1.x = fmaf(w, f01.x, s1.x); s2.x = fmaf(w*f01.x, f01.x, s2.x);
                        s1.y = fmaf(w, f01.y, s1.y); s2.y = fmaf(w*f01.y, f01.y, s2.y);
                        s1.z = fmaf(w, f23.x, s1.z); s2.z = fmaf(w*f23.x, f23.x, s2.z);
                        s1.w = fmaf(w, f23.y, s1.w); s2.w = fmaf(w*f23.y, f23.y, s2.w);
                    }
                }
            }
            ((float4*)(ps1 + part*512))[o1*4 + cq] = s1;
            ((float4*)(ps2 + part*512))[o1*4 + cq] = s2;
        }
    }
    __syncthreads();

    // ---- per-(o,c) stats: 2 rounds over old slot space ----
    #pragma unroll
    for (int round = 0; round < 2; round++) {
        const int slot = t + NT*round;
        const int o = slot >> 4, c = slot & 15;
        const float S1 = ps1[slot] + ps1[512+slot] + ps1[1024+slot] + ps1[1536+slot];
        const float S2 = ps2[slot] + ps2[512+slot] + ps2[1024+slot] + ps2[1536+slot];

        const float rrs = rrs_s[o];
        const float inv = 1.0f / (rrs + EPS);
        const float mean = S1 * inv;
        const float var = (S2 - 2.f*mean*S1 + mean*mean*rrs) * inv;  // exact expansion

        float cj = (beta_v[o] + 0.5f*logf(var + EPS)) * rrs * LNF;
        #pragma unroll
        for (int off = 8; off > 0; off >>= 1)
            cj += __shfl_xor_sync(0xffffffffu, cj, off, 16);

        if (!FINAL) {
            float op2 = -0.5f * logf(TWO_PI * var);
            #pragma unroll
            for (int off = 8; off > 0; off >>= 1)
                op2 += __shfl_xor_sync(0xffffffffu, op2, off, 16);
            if (c == 0) op2_s[o] = op2;
            mean_cs[c*OCAPS + o] = mean;
            i2v_cs[c*OCAPS + o]  = 0.5f / var;
        }
        if (c == 0) cost_s[o] = cj;
        if (FINAL) out[(size_t)tile*512 + slot] = mean;   // poses (tile, o, c)
    }
    __syncthreads();

    if (t < OCAPS) {
        float cost = cost_s[t];
        float cm = cost;
        #pragma unroll
        for (int off = 16; off > 0; off >>= 1)
            cm += __shfl_xor_sync(0xffffffffu, cm, off);
        cm *= (1.0f/32.0f);
        float d = cost - cm;
        float ss = d*d;
        #pragma unroll
        for (int off = 16; off > 0; off >>= 1)
            ss += __shfl_xor_sync(0xffffffffu, ss, off);
        float stdv = sqrtf(ss * (1.0f/32.0f));
        float a = sigmoidf_(lam * (beta_a[t] + (cm - cost)/(stdv + EPS)));
        if (FINAL) out[204800 + tile*OCAPS + t] = a;
        else       logact_s[t] = logf(a + EPS);
    }

    if (FINAL) return;
    __syncthreads();

    // ---- pass 2: z -> buffer RD^1 ; 8 warps x 2 rounds cover k0 = 0..15 ----
    float* Z = g_z[RD ^ 1] + (size_t)tile * ZPT;
    const int o2 = t & 31, w8 = t >> 5;        // w8 in 0..7
    const float zc = logact_s[o2] + op2_s[o2];
    #pragma unroll
    for (int round = 0; round < 2; round++) {
        const int k0 = w8 + 8*round;
        #pragma unroll
        for (int j = 0; j < 9; j++) {
            int k = k0*9 + j;
            const uint4* vp = (const uint4*)(VH + k*512 + o2*CH);
            float s = 0.f;
            #pragma unroll
            for (int h8 = 0; h8 < 2; h8++) {
                union { uint4 u; __half2 h[4]; } cv;
                cv.u = vp[h8];
                #pragma unroll
                for (int q = 0; q < 4; q++) {
                    float2 f = __half22float2(cv.h[q]);
                    int cb = h8*8 + q*2;
                    float d;
                    d = f.x - mean_cs[(cb+0)*OCAPS + o2]; s = fmaf(d*d, i2v_cs[(cb+0)*OCAPS + o2], s);
                    d = f.y - mean_cs[(cb+1)*OCAPS + o2]; s = fmaf(d*d, i2v_cs[(cb+1)*OCAPS + o2], s);
                }
            }
            Z[k*OCAPS + o2] = zc - s;
        }
    }
}

extern "C" void kernel_launch(void* const* d_in, const int* in_sizes, int n_in,
                              void* d_out, int out_size)
{
    const float* votes  = (const float*)d_in[0];
    const float* acti   = (const float*)d_in[1];
    const float* beta_v = (const float*)d_in[2];
    const float* beta_a = (const float*)d_in[3];
    float* out = (float*)d_out;

    const float lam0 = 0.01f * (1.0f - 0.95f);
    const float lam1 = 0.01f * (1.0f - 0.95f*0.95f);
    const float lam2 = 0.01f * (1.0f - 0.95f*0.95f*0.95f);

    // mz0 writes z -> buf 1 ; mz1 reads buf 1, writes buf 0 ; mz2 reads buf 0.
    mz_kernel<true,  false, 0><<<NTILES, NT>>>(votes, acti, beta_v, beta_a, lam0, nullptr);
    mz_kernel<false, false, 1><<<NTILES, NT>>>(votes, acti, beta_v, beta_a, lam1, nullptr);
    mz_kernel<false, true,  0><<<NTILES, NT>>>(votes, acti, beta_v, beta_a, lam2, out);
}

// round 15
// speedup vs baseline: 1.3872x; 1.3872x over previous
#include <cuda_runtime.h>
#include <cuda_fp16.h>
#include <math.h>
#include <math_constants.h>

// EM routing, matrix capsules.
// N=4, child 12x12, kernel 3, stride 1 -> P=10, tiles = 4*100 = 400
// K=144 (9 slots x 16 child caps), O=32 parent caps, ch=16 pose dims.
// votes: (400, 144, 32, 16) f32 ; acts: (400, 144) ; beta_v/beta_a: (32)
// Output: poses (400*32*16 = 204800 floats) then activations (400*32).
//
// R13 structure (256-thread single-wave CTAs, fp16 votes cache, __ldcs on
// the single-use fp32 stream, standalone estep). R15: pass1 load batches
// are software-pipelined (prefetch next 6-load batch into registers before
// computing the current batch) to sustain MLP~6 at the grid-limited 21
// warps/SM. FMA order per accumulator unchanged -> bitwise-identical.

#define NTILES 400
#define KTOT   144
#define OCAPS  32
#define CH     16
#define TILE_ELEMS (KTOT*OCAPS*CH)   // 73728
#define ZPT    (KTOT*OCAPS)          // 4608
#define EPS    1e-9f
#define LNF    22.2222222222222222f  // 100/(144/32)
#define TWO_PI 6.2831853071795864f
#define NCELLS 144                   // 12*12 child cells
#define NT     256

__device__ float g_z   [NTILES*ZPT];              // (tile, k, o)
__device__ float g_m   [4*NCELLS*CH];             // softmax max per (n, cell, cc)
__device__ float g_dinv[4*NCELLS*CH];             // 1/denom per (n, cell, cc)
__device__ uint4 g_vh  [(size_t)NTILES*TILE_ELEMS/8];  // fp16 votes cache (59 MB)

__device__ __forceinline__ float sigmoidf_(float x) { return 1.0f/(1.0f+__expf(-x)); }

template<bool INIT_RR, bool FINAL>
__global__ void __launch_bounds__(NT)
mz_kernel(const float* __restrict__ votes, const float* __restrict__ acti,
          const float* __restrict__ beta_v, const float* __restrict__ beta_a,
          float lam, float* __restrict__ out)
{
    const int tile = blockIdx.x;
    const int n = tile / 100, p = tile % 100;
    const int pr = p / 10, pc = p % 10;
    const float* V = votes + (size_t)tile * TILE_ELEMS;
    __half* VH = ((__half*)g_vh) + (size_t)tile * TILE_ELEMS;

    __shared__ float w_s[ZPT];           // rr*act  [k][o]
    __shared__ float acti_s[KTOT];
    __shared__ float m_s[KTOT];          // softmax max per k (slot,cc)
    __shared__ float dinv_s[KTOT];
    __shared__ float ps1[4*512];         // pass1 partials [part][o*16+c]
    __shared__ float ps2[4*512];
    __shared__ float rp[16*OCAPS];       // rrs partials
    __shared__ float rrs_s[OCAPS];
    __shared__ float mean_cs[CH*OCAPS];  // [c][o]
    __shared__ float i2v_cs[CH*OCAPS];   // 1/(2 var) [c][o]
    __shared__ float cost_s[OCAPS];
    __shared__ float logact_s[OCAPS];
    __shared__ float op2_s[OCAPS];

    const int t = threadIdx.x;
    if (t < KTOT) {
        acti_s[t] = acti[tile*KTOT + t];
        if (!INIT_RR) {
            const int slot = t >> 4, ccp = t & 15;
            const int r = pr + slot/3, ccol = pc + slot%3;
            const int gi = ((n*NCELLS) + r*12 + ccol)*CH + ccp;
            m_s[t]    = g_m[gi];
            dinv_s[t] = g_dinv[gi];
        }
    }
    __syncthreads();

    // ---- build w = rr * act_i ----
    if (INIT_RR) {
        for (int idx = t; idx < ZPT; idx += NT) {
            int k = idx >> 5;
            int slot = k >> 4;
            int r = pr + slot/3, c = pc + slot%3;
            int cr = min(r,9) - max(0,r-2) + 1;
            int cc = min(c,9) - max(0,c-2) + 1;
            float rrv = 1.0f / ((float)(cr*cc) * (float)OCAPS + EPS);
            w_s[idx] = rrv * acti_s[k];
        }
    } else {
        const float* Zown = g_z + (size_t)tile * ZPT;
        for (int idx = t; idx < ZPT; idx += NT) {
            int k = idx >> 5;
            w_s[idx] = __expf(Zown[idx] - m_s[k]) * dinv_s[k] * acti_s[k];
        }
    }
    __syncthreads();

    // ---- rrs partials: 8 warps x 2 rounds cover 16 segs ----
    {
        const int o = t & 31, w = t >> 5;          // w in 0..7
        #pragma unroll
        for (int round = 0; round < 2; round++) {
            const int seg = w + 8*round;
            float sp = 0.f;
            #pragma unroll
            for (int j = 0; j < 9; j++) sp += w_s[(seg*9 + j)*OCAPS + o];
            rp[seg*OCAPS + o] = sp;
        }
    }
    __syncthreads();
    if (t < OCAPS) {
        float s = 0.f;
        #pragma unroll
        for (int i = 0; i < 16; i++) s += rp[i*OCAPS + t];
        rrs_s[t] = s;
    }

    // ---- pass 1: 2 rounds, each = one old (part,o,cq) slot.
    //      Software-pipelined: prefetch batch kb+6 before computing kb. ----
    {
        #pragma unroll
        for (int round = 0; round < 2; round++) {
            const int slot = t + NT*round;          // 0..511
            const int cq = slot & 3, o1 = (slot >> 2) & 31, part = slot >> 7;
            float4 s1 = make_float4(0.f,0.f,0.f,0.f);
            float4 s2 = make_float4(0.f,0.f,0.f,0.f);
            const int kbeg = part * 36;
            if (INIT_RR) {
                const float4* V4 = (const float4*)V;
                float4 cur[6], nxt[6];
                #pragma unroll
                for (int g = 0; g < 6; g++)
                    cur[g] = __ldcs(&V4[(kbeg + g)*128 + o1*4 + cq]);
                for (int kb = 0; kb < 36; kb += 6) {
                    if (kb + 6 < 36) {
                        #pragma unroll
                        for (int g = 0; g < 6; g++)
                            nxt[g] = __ldcs(&V4[(kbeg + kb + 6 + g)*128 + o1*4 + cq]);
                    }
                    #pragma unroll
                    for (int g = 0; g < 6; g++) {
                        const int k = kbeg + kb + g;
                        const float4 v = cur[g];
                        const float w = w_s[k*OCAPS + o1];
                        s1.x = fmaf(w, v.x, s1.x); s2.x = fmaf(w*v.x, v.x, s2.x);
                        s1.y = fmaf(w, v.y, s1.y); s2.y = fmaf(w*v.y, v.y, s2.y);
                        s1.z = fmaf(w, v.z, s1.z); s2.z = fmaf(w*v.z, v.z, s2.z);
                        s1.w = fmaf(w, v.w, s1.w); s2.w = fmaf(w*v.w, v.w, s2.w);
                        union { __half2 h[2]; uint2 u; } cv;
                        cv.h[0] = __floats2half2_rn(v.x, v.y);
                        cv.h[1] = __floats2half2_rn(v.z, v.w);
                        *(uint2*)(VH + k*512 + o1*16 + cq*4) = cv.u;
                    }
                    #pragma unroll
                    for (int g = 0; g < 6; g++) cur[g] = nxt[g];
                }
            } else {
                uint2 cur[6], nxt[6];
                #pragma unroll
                for (int g = 0; g < 6; g++)
                    cur[g] = *(const uint2*)(VH + (kbeg + g)*512 + o1*16 + cq*4);
                for (int kb = 0; kb < 36; kb += 6) {
                    if (kb + 6 < 36) {
                        #pragma unroll
                        for (int g = 0; g < 6; g++)
                            nxt[g] = *(const uint2*)(VH + (kbeg + kb + 6 + g)*512 + o1*16 + cq*4);
                    }
                    #pragma unroll
                    for (int g = 0; g < 6; g++) {
                        const int k = kbeg + kb + g;
                        union { uint2 u; __half2 h[2]; } cv; cv.u = cur[g];
                        float2 f01 = __half22float2(cv.h[0]);
                        float2 f23 = __half22float2(cv.h[1]);
                        const float w = w_s[k*OCAPS + o1];
                        s1.x = fmaf(w, f01.x, s1.x); s2.x = fmaf(w*f01.x, f01.x, s2.x);
                        s1.y = fmaf(w, f01.y, s1.y); s2.y = fmaf(w*f01.y, f01.y, s2.y);
                        s1.z = fmaf(w, f23.x, s1.z); s2.z = fmaf(w*f23.x, f23.x, s2.z);
                        s1.w = fmaf(w, f23.y, s1.w); s2.w = fmaf(w*f23.y, f23.y, s2.w);
                    }
                    #pragma unroll
                    for (int g = 0; g < 6; g++) cur[g] = nxt[g];
                }
            }
            ((float4*)(ps1 + part*512))[o1*4 + cq] = s1;
            ((float4*)(ps2 + part*512))[o1*4 + cq] = s2;
        }
    }
    __syncthreads();

    // ---- per-(o,c) stats: 2 rounds over old slot space ----
    #pragma unroll
    for (int round = 0; round < 2; round++) {
        const int slot = t + NT*round;
        const int o = slot >> 4, c = slot & 15;
        const float S1 = ps1[slot] + ps1[512+slot] + ps1[1024+slot] + ps1[1536+slot];
        const float S2 = ps2[slot] + ps2[512+slot] + ps2[1024+slot] + ps2[1536+slot];

        const float rrs = rrs_s[o];
        const float inv = 1.0f / (rrs + EPS);
        const float mean = S1 * inv;
        const float var = (S2 - 2.f*mean*S1 + mean*mean*rrs) * inv;  // exact expansion

        float cj = (beta_v[o] + 0.5f*logf(var + EPS)) * rrs * LNF;
        #pragma unroll
        for (int off = 8; off > 0; off >>= 1)
            cj += __shfl_xor_sync(0xffffffffu, cj, off, 16);

        if (!FINAL) {
            float op2 = -0.5f * logf(TWO_PI * var);
            #pragma unroll
            for (int off = 8; off > 0; off >>= 1)
                op2 += __shfl_xor_sync(0xffffffffu, op2, off, 16);
            if (c == 0) op2_s[o] = op2;
            mean_cs[c*OCAPS + o] = mean;
            i2v_cs[c*OCAPS + o]  = 0.5f / var;
        }
        if (c == 0) cost_s[o] = cj;
        if (FINAL) out[(size_t)tile*512 + slot] = mean;   // poses (tile, o, c)
    }
    __syncthreads();

    if (t < OCAPS) {
        float cost = cost_s[t];
        float cm = cost;
        #pragma unroll
        for (int off = 16; off > 0; off >>= 1)
            cm += __shfl_xor_sync(0xffffffffu, cm, off);
        cm *= (1.0f/32.0f);
        float d = cost - cm;
        float ss = d*d;
        #pragma unroll
        for (int off = 16; off > 0; off >>= 1)
            ss += __shfl_xor_sync(0xffffffffu, ss, off);
        float stdv = sqrtf(ss * (1.0f/32.0f));
        float a = sigmoidf_(lam * (beta_a[t] + (cm - cost)/(stdv + EPS)));
        if (FINAL) out[204800 + tile*OCAPS + t] = a;
        else       logact_s[t] = logf(a + EPS);
    }

    if (FINAL) return;
    __syncthreads();

    // ---- pass 2: 8 warps x 2 rounds cover k0 = 0..15 ----
    float* Z = g_z + (size_t)tile * ZPT;
    const int o2 = t & 31, w8 = t >> 5;        // w8 in 0..7
    const float zc = logact_s[o2] + op2_s[o2];
    #pragma unroll
    for (int round = 0; round < 2; round++) {
        const int k0 = w8 + 8*round;
        #pragma unroll
        for (int j = 0; j < 9; j++) {
            int k = k0*9 + j;
            const uint4* vp = (const uint4*)(VH + k*512 + o2*CH);
            float s = 0.f;
            #pragma unroll
            for (int h8 = 0; h8 < 2; h8++) {
                union { uint4 u; __half2 h[4]; } cv;
                cv.u = vp[h8];
                #pragma unroll
                for (int q = 0; q < 4; q++) {
                    float2 f = __half22float2(cv.h[q]);
                    int cb = h8*8 + q*2;
                    float d;
                    d = f.x - mean_cs[(cb+0)*OCAPS + o2]; s = fmaf(d*d, i2v_cs[(cb+0)*OCAPS + o2], s);
                    d = f.y - mean_cs[(cb+1)*OCAPS + o2]; s = fmaf(d*d, i2v_cs[(cb+1)*OCAPS + o2], s);
                }
            }
            Z[k*OCAPS + o2] = zc - s;
        }
    }
}

// E-step stats: per (n, child cell, cc): softmax max + 1/denom over
// valid (parent, slot) pairs x 32 parent caps.
// grid = 4*144, 512 threads: warp = one cc (t>>5), lane = o.
__global__ void __launch_bounds__(512)
estep_kernel()
{
    const int b = blockIdx.x;
    const int n = b / NCELLS, c2 = b % NCELLS;
    const int r = c2 / 12, ccol = c2 % 12;
    const int t = threadIdx.x;
    const int cc = t >> 5, o = t & 31;

    float zb[9];
    float m = -CUDART_INF_F;
    #pragma unroll
    for (int dr = 0; dr < 3; dr++) {
        #pragma unroll
        for (int dc = 0; dc < 3; dc++) {
            const int i = dr*3 + dc;
            const int pr2 = r - dr, pc2 = ccol - dc;
            if (pr2 >= 0 && pr2 < 10 && pc2 >= 0 && pc2 < 10) {
                const int p = pr2*10 + pc2;
                const int k = i*CH + cc;
                zb[i] = g_z[((size_t)(n*100 + p))*ZPT + k*OCAPS + o];
                m = fmaxf(m, zb[i]);
            } else {
                zb[i] = -CUDART_INF_F;
            }
        }
    }
    #pragma unroll
    for (int off = 16; off > 0; off >>= 1)
        m = fmaxf(m, __shfl_xor_sync(0xffffffffu, m, off));
    if (isinf(m)) m = 0.0f;

    float s = 0.f;
    #pragma unroll
    for (int i = 0; i < 9; i++)
        s += __expf(zb[i] - m);   // exp(-inf) = 0 for invalid pairs
    #pragma unroll
    for (int off = 16; off > 0; off >>= 1)
        s += __shfl_xor_sync(0xffffffffu, s, off);

    if (o == 0) {
        const int gi = ((n*NCELLS) + c2)*CH + cc;
        g_m[gi]    = m;
        g_dinv[gi] = 1.0f / s;
    }
}

extern "C" void kernel_launch(void* const* d_in, const int* in_sizes, int n_in,
                              void* d_out, int out_size)
{
    const float* votes  = (const float*)d_in[0];
    const float* acti   = (const float*)d_in[1];
    const float* beta_v = (const float*)d_in[2];
    const float* beta_a = (const float*)d_in[3];
    float* out = (float*)d_out;

    const float lam0 = 0.01f * (1.0f - 0.95f);
    const float lam1 = 0.01f * (1.0f - 0.95f*0.95f);
    const float lam2 = 0.01f * (1.0f - 0.95f*0.95f*0.95f);

    mz_kernel<true,  false><<<NTILES, NT>>>(votes, acti, beta_v, beta_a, lam0, nullptr);
    estep_kernel<<<4*NCELLS, 512>>>();
    mz_kernel<false, false><<<NTILES, NT>>>(votes, acti, beta_v, beta_a, lam1, nullptr);
    estep_kernel<<<4*NCELLS, 512>>>();
    mz_kernel<false, true ><<<NTILES, NT>>>(votes, acti, beta_v, beta_a, lam2, out);
}